// round 11
// baseline (speedup 1.0000x reference)
#include <cuda_runtime.h>
#include <cuda_fp16.h>
#include <cstdint>
#include <cstring>

// NT-Xent contrastive loss, sm_103 baseline ISA. fp16 HMMA (f16 acc), 512-thread
// CTA (4 warps/SMSP) to test latency- vs throughput-bound legacy tensor pipe.
// Symmetric tiles (I<=J): row sums -> band I, col sums -> band J, u64 fixed-point
// atomics (deterministic). loss = mean( ln(S_i - diag_i) - pos_i ).

#define N2    8192
#define DD    128
#define NHALF 4096
#define RSTRIDE 272
#define TILE_SM (128 * RSTRIDE)          // 34816
#define SM_COLRED (4 * TILE_SM)          // A + 3 B stages before colred
#define SMEM_TOTAL (4 * TILE_SM + 2048)  // 141312
#define FXS  68719476736.0f              // 2^36 (exp-sum fixed point)
#define FXL  1099511627776.0f            // 2^40 (loss-term fixed point)

__device__ __align__(16) __half g_znA[(size_t)N2 * DD];  // * 2*log2(e)
__device__ __align__(16) __half g_znB[(size_t)N2 * DD];
__device__ unsigned long long g_S[N2];
__device__ unsigned long long g_acc;
__device__ unsigned int g_tick;
__device__ float g_pos[N2];
__device__ float g_diag[N2];

// ---------------- PTX helpers ----------------
__device__ __forceinline__ uint32_t smem_u32(const void* p) {
    uint32_t a;
    asm("{ .reg .u64 t; cvta.to.shared.u64 t, %1; cvt.u32.u64 %0, t; }" : "=r"(a) : "l"(p));
    return a;
}
__device__ __forceinline__ void cp16(uint32_t dst, const void* src) {
    asm volatile("cp.async.cg.shared.global [%0], [%1], 16;" :: "r"(dst), "l"(src));
}
#define CP_COMMIT() asm volatile("cp.async.commit_group;" ::: "memory")
#define CP_WAIT2()  asm volatile("cp.async.wait_group 2;" ::: "memory")
#define CP_WAIT1()  asm volatile("cp.async.wait_group 1;" ::: "memory")
#define CP_WAIT0()  asm volatile("cp.async.wait_group 0;" ::: "memory")

#define LDSM4(r0, r1, r2, r3, addr)                                              \
    asm volatile("ldmatrix.sync.aligned.m8n8.x4.shared.b16 {%0,%1,%2,%3}, [%4];" \
                 : "=r"(r0), "=r"(r1), "=r"(r2), "=r"(r3) : "r"(addr))

// f16 accumulators: c[0]=row r cols (c,c+1); c[1]=row r+8.
#define MMA16816H(c, a, b0, b1)                                                \
    asm volatile("mma.sync.aligned.m16n8k16.row.col.f16.f16.f16.f16 "          \
                 "{%0,%1}, {%2,%3,%4,%5}, {%6,%7}, {%0,%1};"                   \
                 : "+r"((c)[0]), "+r"((c)[1])                                  \
                 : "r"((a)[0]), "r"((a)[1]), "r"((a)[2]), "r"((a)[3]),         \
                   "r"(b0), "r"(b1))

__device__ __forceinline__ float fast_lg2(float x) {
    float y; asm("lg2.approx.f32 %0, %1;" : "=f"(y) : "f"(x)); return y;
}
__device__ __forceinline__ __half2 u2h2(uint32_t u) {
    __half2 h; memcpy(&h, &u, 4); return h;
}

// ---------------- 1) prep ----------------
__global__ void prep_kernel(const float* __restrict__ zi, const float* __restrict__ zj) {
    int gtid = blockIdx.x * blockDim.x + threadIdx.x;
    if (gtid < N2) g_S[gtid] = 0ull;
    if (gtid == 0) { g_acc = 0ull; g_tick = 0u; }
    int w    = gtid >> 5;
    int lane = threadIdx.x & 31;
    if (w >= NHALF) return;
    float4 a = reinterpret_cast<const float4*>(zi + (size_t)w * DD)[lane];
    float4 b = reinterpret_cast<const float4*>(zj + (size_t)w * DD)[lane];
    float sa = a.x * a.x + a.y * a.y + a.z * a.z + a.w * a.w;
    float sb = b.x * b.x + b.y * b.y + b.z * b.z + b.w * b.w;
    float dp = a.x * b.x + a.y * b.y + a.z * b.z + a.w * b.w;
#pragma unroll
    for (int o = 16; o > 0; o >>= 1) {
        sa += __shfl_xor_sync(0xffffffffu, sa, o);
        sb += __shfl_xor_sync(0xffffffffu, sb, o);
        dp += __shfl_xor_sync(0xffffffffu, dp, o);
    }
    float ia = rsqrtf(sa), ib = rsqrtf(sb);
    const float CA = 2.8853900817779268f;   // 2*log2(e)
    float iaC = ia * CA, ibC = ib * CA;

    __half sA[4], pA[4], sB[4], pB[4];
    sA[0]=__float2half_rn(a.x*iaC); sA[1]=__float2half_rn(a.y*iaC);
    sA[2]=__float2half_rn(a.z*iaC); sA[3]=__float2half_rn(a.w*iaC);
    pA[0]=__float2half_rn(a.x*ia);  pA[1]=__float2half_rn(a.y*ia);
    pA[2]=__float2half_rn(a.z*ia);  pA[3]=__float2half_rn(a.w*ia);
    sB[0]=__float2half_rn(b.x*ibC); sB[1]=__float2half_rn(b.y*ibC);
    sB[2]=__float2half_rn(b.z*ibC); sB[3]=__float2half_rn(b.w*ibC);
    pB[0]=__float2half_rn(b.x*ib);  pB[1]=__float2half_rn(b.y*ib);
    pB[2]=__float2half_rn(b.z*ib);  pB[3]=__float2half_rn(b.w*ib);

    float da = 0.f, db = 0.f;
#pragma unroll
    for (int k = 0; k < 4; ++k) {
        da += __half2float(sA[k]) * __half2float(pA[k]);
        db += __half2float(sB[k]) * __half2float(pB[k]);
    }
#pragma unroll
    for (int o = 16; o > 0; o >>= 1) {
        da += __shfl_xor_sync(0xffffffffu, da, o);
        db += __shfl_xor_sync(0xffffffffu, db, o);
    }
    if (lane == 0) {
        float p = 2.0f * dp * ia * ib;
        g_pos[w] = p; g_pos[w + NHALF] = p;
        g_diag[w]         = exp2f(da);
        g_diag[w + NHALF] = exp2f(db);
    }
    uint2 u;
    memcpy(&u, sA, 8); reinterpret_cast<uint2*>(g_znA + (size_t)w * DD)[lane] = u;
    memcpy(&u, pA, 8); reinterpret_cast<uint2*>(g_znB + (size_t)w * DD)[lane] = u;
    memcpy(&u, sB, 8); reinterpret_cast<uint2*>(g_znA + (size_t)(w + NHALF) * DD)[lane] = u;
    memcpy(&u, pB, 8); reinterpret_cast<uint2*>(g_znB + (size_t)(w + NHALF) * DD)[lane] = u;
}

// ---------------- 2) fused symmetric HMMA + exp2, 512 threads ----------------
__device__ __forceinline__ void load_tile(uint32_t dstBase, const __half* src, int tid) {
#pragma unroll
    for (int p = 0; p < 4; ++p) {
        int id = p * 512 + tid;          // 0..2047 chunks of 16B
        int row = id >> 4, ch = id & 15;
        cp16(dstBase + row * RSTRIDE + ch * 16,
             reinterpret_cast<const char*>(src) + row * 256 + ch * 16);
    }
}

__global__ __launch_bounds__(512, 1) void simlse_kernel() {
    extern __shared__ unsigned char smem[];
    const uint32_t sb   = smem_u32(smem);
    const uint32_t smA  = sb;
    const uint32_t smB0 = sb + TILE_SM;                          // 3 stages
    float* colred = reinterpret_cast<float*>(smem + SM_COLRED);  // [4 wm][128]

    const int tid = threadIdx.x, wid = tid >> 5, lane = tid & 31;
    const int bi    = blockIdx.x >> 2;
    const int chunk = blockIdx.x & 3;
    const int wm = wid >> 2;           // 4 row groups (32 rows each)
    const int wn = wid & 3;            // 4 col groups (32 cols each)

    const uint32_t aOff = (uint32_t)(lane & 15) * RSTRIDE + (uint32_t)((lane >> 4) << 4);
    const uint32_t bOff = (uint32_t)((lane & 7) + ((lane & 16) ? 8 : 0)) * RSTRIDE +
                          (uint32_t)((lane & 8) ? 16 : 0);
    const __half2 zero2 = __float2half2_rn(0.f);

#pragma unroll 1
    for (int phase = 0; phase < 2; ++phase) {
        const int I = phase ? (63 - bi) : bi;
        const int nJ = (I + chunk <= 63) ? ((63 - I - chunk) / 4 + 1) : 0;
        if (nJ <= 0) continue;

        __syncthreads();   // previous-phase reads complete
        load_tile(smA, g_znA + (size_t)I * 128 * DD, tid);
        CP_COMMIT();
        load_tile(smB0, g_znB + (size_t)(I + chunk) * 128 * DD, tid);
        CP_COMMIT();
        if (nJ > 1)
            load_tile(smB0 + TILE_SM, g_znB + (size_t)(I + chunk + 4) * 128 * DD, tid);
        CP_COMMIT();
        CP_WAIT2();
        __syncthreads();

        // A fragments resident: 32 rows x 128 k = 64 regs
        uint32_t afr[2][8][4];
        {
            const uint32_t aBase = smA + (uint32_t)(wm * 32) * RSTRIDE + aOff;
#pragma unroll
            for (int mb = 0; mb < 2; ++mb)
#pragma unroll
                for (int ks = 0; ks < 8; ++ks)
                    LDSM4(afr[mb][ks][0], afr[mb][ks][1], afr[mb][ks][2], afr[mb][ks][3],
                          aBase + (uint32_t)(mb * 16) * RSTRIDE + (uint32_t)(ks * 32));
        }

        float frow[2][2] = {{0.f,0.f},{0.f,0.f}};

#pragma unroll 1
        for (int t = 0; t < nJ; ++t) {
            const int J = I + chunk + 4 * t;
            const int s = t % 3;
            CP_WAIT1();
            __syncthreads();
            if (t + 2 < nJ)
                load_tile(smB0 + (uint32_t)((t + 2) % 3) * TILE_SM,
                          g_znB + (size_t)(J + 8) * 128 * DD, tid);
            CP_COMMIT();

            __half2 cs[2][2] = {{zero2, zero2}, {zero2, zero2}};
            __half2 sumr0[2] = {zero2, zero2};   // rows r
            __half2 sumr8[2] = {zero2, zero2};   // rows r+8
#pragma unroll
            for (int np = 0; np < 2; ++np) {
                const uint32_t bBase = smB0 + (uint32_t)s * TILE_SM +
                                       (uint32_t)(wn * 32 + np * 16) * RSTRIDE + bOff;
                uint32_t bfr[8][4];
#pragma unroll
                for (int ks = 0; ks < 8; ++ks)
                    LDSM4(bfr[ks][0], bfr[ks][1], bfr[ks][2], bfr[ks][3],
                          bBase + (uint32_t)(ks * 32));

                uint32_t acc[2][2][2];
#pragma unroll
                for (int mb = 0; mb < 2; ++mb)
#pragma unroll
                    for (int nb = 0; nb < 2; ++nb) { acc[mb][nb][0] = 0u; acc[mb][nb][1] = 0u; }
#pragma unroll
                for (int ks = 0; ks < 8; ++ks)
#pragma unroll
                    for (int mb = 0; mb < 2; ++mb) {
                        MMA16816H(acc[mb][0], afr[mb][ks], bfr[ks][0], bfr[ks][1]);
                        MMA16816H(acc[mb][1], afr[mb][ks], bfr[ks][2], bfr[ks][3]);
                    }
#pragma unroll
                for (int mb = 0; mb < 2; ++mb)
#pragma unroll
                    for (int nb = 0; nb < 2; ++nb) {
                        __half2 e0 = h2exp2(u2h2(acc[mb][nb][0]));
                        __half2 e1 = h2exp2(u2h2(acc[mb][nb][1]));
                        sumr0[mb] = __hadd2(sumr0[mb], e0);
                        sumr8[mb] = __hadd2(sumr8[mb], e1);
                        cs[np][nb] = __hadd2(cs[np][nb], __hadd2(e0, e1));
                    }
            }
            // rows -> fp32 accumulators
#pragma unroll
            for (int mb = 0; mb < 2; ++mb) {
                float2 f0 = __half22float2(sumr0[mb]);
                float2 f1 = __half22float2(sumr8[mb]);
                frow[mb][0] += f0.x + f0.y;
                frow[mb][1] += f1.x + f1.y;
            }
            // cols: reduce over quad-rows (xor 4,8,16); lanes 0..3 publish col pairs
#pragma unroll
            for (int np = 0; np < 2; ++np)
#pragma unroll
                for (int nb = 0; nb < 2; ++nb) {
                    __half2 v = cs[np][nb];
                    v = __hadd2(v, __shfl_xor_sync(0xffffffffu, v, 4));
                    v = __hadd2(v, __shfl_xor_sync(0xffffffffu, v, 8));
                    v = __hadd2(v, __shfl_xor_sync(0xffffffffu, v, 16));
                    if (lane < 4) {
                        float2 f = __half22float2(v);
                        int c = wn * 32 + np * 16 + nb * 8 + lane * 2;
                        colred[wm * 128 + c + 0] = f.x;
                        colred[wm * 128 + c + 1] = f.y;
                    }
                }
            __syncthreads();   // colred ready; stage-s reads complete
            if (J != I && tid < 128) {
                float v = colred[tid] + colred[128 + tid] +
                          colred[256 + tid] + colred[384 + tid];
                atomicAdd(&g_S[J * 128 + tid], __float2ull_rn(v * FXS));
            }
        }

        // ---- row flush for band I (quad reduce + direct atomics) ----
#pragma unroll
        for (int mb = 0; mb < 2; ++mb)
#pragma unroll
            for (int h = 0; h < 2; ++h) {
                frow[mb][h] += __shfl_xor_sync(0xffffffffu, frow[mb][h], 1);
                frow[mb][h] += __shfl_xor_sync(0xffffffffu, frow[mb][h], 2);
            }
        if ((lane & 3) == 0) {
            int q = lane >> 2;
            int rbase = I * 128 + wm * 32 + q;
#pragma unroll
            for (int mb = 0; mb < 2; ++mb) {
                atomicAdd(&g_S[rbase + mb * 16 + 0], __float2ull_rn(frow[mb][0] * FXS));
                atomicAdd(&g_S[rbase + mb * 16 + 8], __float2ull_rn(frow[mb][1] * FXS));
            }
        }
    }
    CP_WAIT0();
}

// ---------------- 3) finish: 8 blocks, last block writes ----------------
__global__ void finish_kernel(float* __restrict__ out) {
    const int t = threadIdx.x;
    const int i = blockIdx.x * 1024 + t;
    const float LN2 = 0.6931471805599453f;
    float S = __ull2float_rn(g_S[i]) * (1.0f / FXS);
    float term = fast_lg2(S - g_diag[i]) * LN2 - g_pos[i];
    unsigned long long fx = __float2ull_rn(term * FXL);
#pragma unroll
    for (int o = 16; o > 0; o >>= 1)
        fx += __shfl_xor_sync(0xffffffffu, fx, o);
    if ((t & 31) == 0) atomicAdd(&g_acc, fx);
    __threadfence();
    __syncthreads();
    if (t == 0) {
        unsigned int tk = atomicAdd(&g_tick, 1u);
        if (tk == gridDim.x - 1) {
            __threadfence();
            unsigned long long total = atomicAdd(&g_acc, 0ull);
            out[0] = (float)((double)total * (1.0 / 1099511627776.0) / (double)N2);
        }
    }
}

// ---------------- launch ----------------
extern "C" void kernel_launch(void* const* d_in, const int* in_sizes, int n_in,
                              void* d_out, int out_size) {
    const float* zi = (const float*)d_in[0];
    const float* zj = (const float*)d_in[1];
    cudaFuncSetAttribute(simlse_kernel, cudaFuncAttributeMaxDynamicSharedMemorySize,
                         SMEM_TOTAL);
    prep_kernel<<<NHALF / 8, 256>>>(zi, zj);
    simlse_kernel<<<128, 512, SMEM_TOTAL>>>();
    finish_kernel<<<N2 / 1024, 1024>>>((float*)d_out);
}

// round 12
// speedup vs baseline: 1.0565x; 1.0565x over previous
#include <cuda_runtime.h>
#include <cuda_fp16.h>
#include <cstdint>
#include <cstring>

// NT-Xent contrastive loss, sm_103 baseline ISA. fp16 HMMA (f16 acc).
// Symmetric 128x128 tiles (I<=J), pair-major flattened schedule over 148 CTAs:
// pair p = (band p, band 63-p) has exactly 65 tiles; 2080 tiles = 148*14+8.
// Row sums -> band I, col sums -> band J, u64 fixed-point atomics (deterministic).
// loss = mean( ln(S_i - diag_i) - pos_i ).

#define N2    8192
#define DD    128
#define NHALF 4096
#define RSTRIDE 272
#define TILE_SM (128 * RSTRIDE)          // 34816
#define SM_COLRED (4 * TILE_SM)          // A + 3 B stages before colred
#define SMEM_TOTAL (4 * TILE_SM + 1024)  // 140288
#define FXS  68719476736.0f              // 2^36 (exp-sum fixed point)
#define FXL  1099511627776.0f            // 2^40 (loss-term fixed point)
#define NCTA 148

__device__ __align__(16) __half g_znA[(size_t)N2 * DD];  // * 2*log2(e)
__device__ __align__(16) __half g_znB[(size_t)N2 * DD];
__device__ unsigned long long g_S[N2];
__device__ unsigned long long g_acc;
__device__ unsigned int g_tick;
__device__ float g_pos[N2];
__device__ float g_diag[N2];

// ---------------- PTX helpers ----------------
__device__ __forceinline__ uint32_t smem_u32(const void* p) {
    uint32_t a;
    asm("{ .reg .u64 t; cvta.to.shared.u64 t, %1; cvt.u32.u64 %0, t; }" : "=r"(a) : "l"(p));
    return a;
}
__device__ __forceinline__ void cp16(uint32_t dst, const void* src) {
    asm volatile("cp.async.cg.shared.global [%0], [%1], 16;" :: "r"(dst), "l"(src));
}
#define CP_COMMIT() asm volatile("cp.async.commit_group;" ::: "memory")
#define CP_WAIT2()  asm volatile("cp.async.wait_group 2;" ::: "memory")
#define CP_WAIT1()  asm volatile("cp.async.wait_group 1;" ::: "memory")
#define CP_WAIT0()  asm volatile("cp.async.wait_group 0;" ::: "memory")

#define LDSM4(r0, r1, r2, r3, addr)                                              \
    asm volatile("ldmatrix.sync.aligned.m8n8.x4.shared.b16 {%0,%1,%2,%3}, [%4];" \
                 : "=r"(r0), "=r"(r1), "=r"(r2), "=r"(r3) : "r"(addr))

// f16 accumulators: c[0]=row r cols (c,c+1); c[1]=row r+8.
#define MMA16816H(c, a, b0, b1)                                                \
    asm volatile("mma.sync.aligned.m16n8k16.row.col.f16.f16.f16.f16 "          \
                 "{%0,%1}, {%2,%3,%4,%5}, {%6,%7}, {%0,%1};"                   \
                 : "+r"((c)[0]), "+r"((c)[1])                                  \
                 : "r"((a)[0]), "r"((a)[1]), "r"((a)[2]), "r"((a)[3]),         \
                   "r"(b0), "r"(b1))

__device__ __forceinline__ float fast_lg2(float x) {
    float y; asm("lg2.approx.f32 %0, %1;" : "=f"(y) : "f"(x)); return y;
}
__device__ __forceinline__ __half2 u2h2(uint32_t u) {
    __half2 h; memcpy(&h, &u, 4); return h;
}

// ---------------- 1) prep ----------------
__global__ void prep_kernel(const float* __restrict__ zi, const float* __restrict__ zj) {
    int gtid = blockIdx.x * blockDim.x + threadIdx.x;
    if (gtid < N2) g_S[gtid] = 0ull;
    if (gtid == 0) { g_acc = 0ull; g_tick = 0u; }
    int w    = gtid >> 5;
    int lane = threadIdx.x & 31;
    if (w >= NHALF) return;
    float4 a = reinterpret_cast<const float4*>(zi + (size_t)w * DD)[lane];
    float4 b = reinterpret_cast<const float4*>(zj + (size_t)w * DD)[lane];
    float sa = a.x * a.x + a.y * a.y + a.z * a.z + a.w * a.w;
    float sb = b.x * b.x + b.y * b.y + b.z * b.z + b.w * b.w;
    float dp = a.x * b.x + a.y * b.y + a.z * b.z + a.w * b.w;
#pragma unroll
    for (int o = 16; o > 0; o >>= 1) {
        sa += __shfl_xor_sync(0xffffffffu, sa, o);
        sb += __shfl_xor_sync(0xffffffffu, sb, o);
        dp += __shfl_xor_sync(0xffffffffu, dp, o);
    }
    float ia = rsqrtf(sa), ib = rsqrtf(sb);
    const float CA = 2.8853900817779268f;   // 2*log2(e)
    float iaC = ia * CA, ibC = ib * CA;

    __half sA[4], pA[4], sB[4], pB[4];
    sA[0]=__float2half_rn(a.x*iaC); sA[1]=__float2half_rn(a.y*iaC);
    sA[2]=__float2half_rn(a.z*iaC); sA[3]=__float2half_rn(a.w*iaC);
    pA[0]=__float2half_rn(a.x*ia);  pA[1]=__float2half_rn(a.y*ia);
    pA[2]=__float2half_rn(a.z*ia);  pA[3]=__float2half_rn(a.w*ia);
    sB[0]=__float2half_rn(b.x*ibC); sB[1]=__float2half_rn(b.y*ibC);
    sB[2]=__float2half_rn(b.z*ibC); sB[3]=__float2half_rn(b.w*ibC);
    pB[0]=__float2half_rn(b.x*ib);  pB[1]=__float2half_rn(b.y*ib);
    pB[2]=__float2half_rn(b.z*ib);  pB[3]=__float2half_rn(b.w*ib);

    float da = 0.f, db = 0.f;
#pragma unroll
    for (int k = 0; k < 4; ++k) {
        da += __half2float(sA[k]) * __half2float(pA[k]);
        db += __half2float(sB[k]) * __half2float(pB[k]);
    }
#pragma unroll
    for (int o = 16; o > 0; o >>= 1) {
        da += __shfl_xor_sync(0xffffffffu, da, o);
        db += __shfl_xor_sync(0xffffffffu, db, o);
    }
    if (lane == 0) {
        float p = 2.0f * dp * ia * ib;
        g_pos[w] = p; g_pos[w + NHALF] = p;
        g_diag[w]         = exp2f(da);
        g_diag[w + NHALF] = exp2f(db);
    }
    uint2 u;
    memcpy(&u, sA, 8); reinterpret_cast<uint2*>(g_znA + (size_t)w * DD)[lane] = u;
    memcpy(&u, pA, 8); reinterpret_cast<uint2*>(g_znB + (size_t)w * DD)[lane] = u;
    memcpy(&u, sB, 8); reinterpret_cast<uint2*>(g_znA + (size_t)(w + NHALF) * DD)[lane] = u;
    memcpy(&u, pB, 8); reinterpret_cast<uint2*>(g_znB + (size_t)(w + NHALF) * DD)[lane] = u;
}

// ---------------- 2) fused symmetric HMMA + exp2, flattened schedule ----------------
__device__ __forceinline__ void load_tile(uint32_t dstBase, const __half* src, int tid) {
#pragma unroll
    for (int p = 0; p < 8; ++p) {
        int id = p * 256 + tid;
        int row = id >> 4, ch = id & 15;
        cp16(dstBase + row * RSTRIDE + ch * 16,
             reinterpret_cast<const char*>(src) + row * 256 + ch * 16);
    }
}

__global__ __launch_bounds__(256, 1) void simlse_kernel() {
    extern __shared__ unsigned char smem[];
    const uint32_t sb   = smem_u32(smem);
    const uint32_t smA  = sb;
    const uint32_t smB0 = sb + TILE_SM;                          // 3 stages
    float* colred = reinterpret_cast<float*>(smem + SM_COLRED);  // [2 wm][128]

    const int tid = threadIdx.x, wid = tid >> 5, lane = tid & 31;
    const int wn = wid & 3, wm = wid >> 2;
    const int bx = blockIdx.x;

    // contiguous tile range in pair-major order (pair p = bands {p, 63-p}, 65 tiles)
    int t    = bx * 14 + (bx < 8 ? bx : 8);
    int tEnd = t + 14 + (bx < 8 ? 1 : 0);

    const uint32_t aOff = (uint32_t)(lane & 15) * RSTRIDE + (uint32_t)((lane >> 4) << 4);
    const uint32_t bOff = (uint32_t)((lane & 7) + ((lane & 16) ? 8 : 0)) * RSTRIDE +
                          (uint32_t)((lane & 8) ? 16 : 0);
    const __half2 zero2 = __float2half2_rn(0.f);

#pragma unroll 1
    while (t < tEnd) {
        // decode tile t -> (I, J0, run length n)
        int q = t / 65, r = t - q * 65;
        int len1 = 64 - q;
        int I, J0, navail;
        if (r < len1) { I = q;      J0 = q + r;            navail = len1 - r; }
        else          { int r2 = r - len1;
                        I = 63 - q; J0 = I + r2;           navail = (q + 1) - r2; }
        const int n = (tEnd - t < navail) ? (tEnd - t) : navail;
        t += n;

        // ---- run prologue: A + first two B tiles ----
        __syncthreads();   // previous-run reads complete
        load_tile(smA, g_znA + (size_t)I * 128 * DD, tid);
        CP_COMMIT();
        load_tile(smB0, g_znB + (size_t)J0 * 128 * DD, tid);
        CP_COMMIT();
        if (n > 1)
            load_tile(smB0 + TILE_SM, g_znB + (size_t)(J0 + 1) * 128 * DD, tid);
        CP_COMMIT();
        CP_WAIT2();
        __syncthreads();

        uint32_t afr[4][8][4];
        {
            const uint32_t aBase = smA + (uint32_t)(wm * 64) * RSTRIDE + aOff;
#pragma unroll
            for (int mb = 0; mb < 4; ++mb)
#pragma unroll
                for (int ks = 0; ks < 8; ++ks)
                    LDSM4(afr[mb][ks][0], afr[mb][ks][1], afr[mb][ks][2], afr[mb][ks][3],
                          aBase + (uint32_t)(mb * 16) * RSTRIDE + (uint32_t)(ks * 32));
        }

        float frow[4][2] = {{0.f,0.f},{0.f,0.f},{0.f,0.f},{0.f,0.f}};

#pragma unroll 1
        for (int tt = 0; tt < n; ++tt) {
            const int J = J0 + tt;
            const int s = tt % 3;
            CP_WAIT1();
            __syncthreads();
            if (tt + 2 < n)
                load_tile(smB0 + (uint32_t)((tt + 2) % 3) * TILE_SM,
                          g_znB + (size_t)(J + 2) * 128 * DD, tid);
            CP_COMMIT();

            __half2 cs[2][2] = {{zero2, zero2}, {zero2, zero2}};
            __half2 sumr0[4] = {zero2, zero2, zero2, zero2};
            __half2 sumr8[4] = {zero2, zero2, zero2, zero2};
#pragma unroll
            for (int np = 0; np < 2; ++np) {
                const uint32_t bBase = smB0 + (uint32_t)s * TILE_SM +
                                       (uint32_t)(wn * 32 + np * 16) * RSTRIDE + bOff;
                uint32_t bfr[8][4];
#pragma unroll
                for (int ks = 0; ks < 8; ++ks)
                    LDSM4(bfr[ks][0], bfr[ks][1], bfr[ks][2], bfr[ks][3],
                          bBase + (uint32_t)(ks * 32));

                uint32_t acc[4][2][2];
#pragma unroll
                for (int mb = 0; mb < 4; ++mb)
#pragma unroll
                    for (int nb = 0; nb < 2; ++nb) { acc[mb][nb][0] = 0u; acc[mb][nb][1] = 0u; }
#pragma unroll
                for (int ks = 0; ks < 8; ++ks)
#pragma unroll
                    for (int mb = 0; mb < 4; ++mb) {
                        MMA16816H(acc[mb][0], afr[mb][ks], bfr[ks][0], bfr[ks][1]);
                        MMA16816H(acc[mb][1], afr[mb][ks], bfr[ks][2], bfr[ks][3]);
                    }
#pragma unroll
                for (int mb = 0; mb < 4; ++mb)
#pragma unroll
                    for (int nb = 0; nb < 2; ++nb) {
                        __half2 e0 = h2exp2(u2h2(acc[mb][nb][0]));
                        __half2 e1 = h2exp2(u2h2(acc[mb][nb][1]));
                        sumr0[mb] = __hadd2(sumr0[mb], e0);
                        sumr8[mb] = __hadd2(sumr8[mb], e1);
                        cs[np][nb] = __hadd2(cs[np][nb], __hadd2(e0, e1));
                    }
            }
            // rows -> fp32 accumulators
#pragma unroll
            for (int mb = 0; mb < 4; ++mb) {
                float2 f0 = __half22float2(sumr0[mb]);
                float2 f1 = __half22float2(sumr8[mb]);
                frow[mb][0] += f0.x + f0.y;
                frow[mb][1] += f1.x + f1.y;
            }
            // cols: reduce over row groups; lanes 0..3 publish col pairs
#pragma unroll
            for (int np = 0; np < 2; ++np)
#pragma unroll
                for (int nb = 0; nb < 2; ++nb) {
                    __half2 v = cs[np][nb];
                    v = __hadd2(v, __shfl_xor_sync(0xffffffffu, v, 4));
                    v = __hadd2(v, __shfl_xor_sync(0xffffffffu, v, 8));
                    v = __hadd2(v, __shfl_xor_sync(0xffffffffu, v, 16));
                    if (lane < 4) {
                        float2 f = __half22float2(v);
                        int c = wn * 32 + np * 16 + nb * 8 + lane * 2;
                        colred[wm * 128 + c + 0] = f.x;
                        colred[wm * 128 + c + 1] = f.y;
                    }
                }
            __syncthreads();   // colred ready; stage-s reads complete
            if (J != I && tid < 128) {
                float v = colred[tid] + colred[128 + tid];
                atomicAdd(&g_S[J * 128 + tid], __float2ull_rn(v * FXS));
            }
        }

        // ---- row flush for band I (per run) ----
#pragma unroll
        for (int mb = 0; mb < 4; ++mb)
#pragma unroll
            for (int h = 0; h < 2; ++h) {
                frow[mb][h] += __shfl_xor_sync(0xffffffffu, frow[mb][h], 1);
                frow[mb][h] += __shfl_xor_sync(0xffffffffu, frow[mb][h], 2);
            }
        if ((lane & 3) == 0) {
            int qd = lane >> 2;
            int rbase = I * 128 + wm * 64 + qd;
#pragma unroll
            for (int mb = 0; mb < 4; ++mb) {
                atomicAdd(&g_S[rbase + mb * 16 + 0], __float2ull_rn(frow[mb][0] * FXS));
                atomicAdd(&g_S[rbase + mb * 16 + 8], __float2ull_rn(frow[mb][1] * FXS));
            }
        }
    }
    CP_WAIT0();
}

// ---------------- 3) finish: 8 blocks, last block writes ----------------
__global__ void finish_kernel(float* __restrict__ out) {
    const int t = threadIdx.x;
    const int i = blockIdx.x * 1024 + t;
    const float LN2 = 0.6931471805599453f;
    float S = __ull2float_rn(g_S[i]) * (1.0f / FXS);
    float term = fast_lg2(S - g_diag[i]) * LN2 - g_pos[i];
    unsigned long long fx = __float2ull_rn(term * FXL);
#pragma unroll
    for (int o = 16; o > 0; o >>= 1)
        fx += __shfl_xor_sync(0xffffffffu, fx, o);
    if ((t & 31) == 0) atomicAdd(&g_acc, fx);
    __threadfence();
    __syncthreads();
    if (t == 0) {
        unsigned int tk = atomicAdd(&g_tick, 1u);
        if (tk == gridDim.x - 1) {
            __threadfence();
            unsigned long long total = atomicAdd(&g_acc, 0ull);
            out[0] = (float)((double)total * (1.0 / 1099511627776.0) / (double)N2);
        }
    }
}

// ---------------- launch ----------------
extern "C" void kernel_launch(void* const* d_in, const int* in_sizes, int n_in,
                              void* d_out, int out_size) {
    const float* zi = (const float*)d_in[0];
    const float* zj = (const float*)d_in[1];
    cudaFuncSetAttribute(simlse_kernel, cudaFuncAttributeMaxDynamicSharedMemorySize,
                         SMEM_TOTAL);
    prep_kernel<<<NHALF / 8, 256>>>(zi, zj);
    simlse_kernel<<<NCTA, 256, SMEM_TOTAL>>>();
    finish_kernel<<<N2 / 1024, 1024>>>((float*)d_out);
}